// round 1
// baseline (speedup 1.0000x reference)
#include <cuda_runtime.h>
#include <cstdint>

#define B_  64
#define N_  197
#define D_  768
#define H_  12
#define DH_ 64
#define C3  2304          // 3*H*DH
#define MASK_VAL -987654321.0f

// Scratch buffers (device globals: allocation-free contract)
__device__ float g_qkv [B_ * N_ * C3];   // 29,048,832 floats (~116 MB)
__device__ float g_attn[B_ * N_ * D_];   //  9,682,944 floats (~39 MB)

// ---------------------------------------------------------------------------
// SGEMM (NT): C[m,n] = sum_k A[m,k] * B[n,k] (+ bias[n])
// Both operands row-major with K contiguous. 128x128x16 tile, 8x8 per thread.
// ---------------------------------------------------------------------------
__global__ void __launch_bounds__(256)
sgemm_nt(const float* __restrict__ A, const float* __restrict__ Bm,
         const float* __restrict__ bias, float* __restrict__ C,
         int M, int N, int K) {
    __shared__ float As[16][128];
    __shared__ float Bs[16][128];

    const int tid = threadIdx.x;
    const int tx = tid & 15;          // 0..15 -> N micro-tile
    const int ty = tid >> 4;          // 0..15 -> M micro-tile
    const int rowBase = blockIdx.y * 128;
    const int colBase = blockIdx.x * 128;

    const int lr = tid >> 2;          // 0..63  (row within half-tile)
    const int lc = (tid & 3) * 4;     // 0,4,8,12 (k offset, float4)

    float acc[8][8];
    #pragma unroll
    for (int i = 0; i < 8; ++i)
        #pragma unroll
        for (int j = 0; j < 8; ++j) acc[i][j] = 0.0f;

    for (int k0 = 0; k0 < K; k0 += 16) {
        #pragma unroll
        for (int hv = 0; hv < 2; ++hv) {
            const int r  = lr + hv * 64;
            const int gm = rowBase + r;
            float4 av = make_float4(0.f, 0.f, 0.f, 0.f);
            if (gm < M) av = *(const float4*)(A + (size_t)gm * K + k0 + lc);
            As[lc + 0][r] = av.x; As[lc + 1][r] = av.y;
            As[lc + 2][r] = av.z; As[lc + 3][r] = av.w;

            const int gn = colBase + r;
            float4 bv = make_float4(0.f, 0.f, 0.f, 0.f);
            if (gn < N) bv = *(const float4*)(Bm + (size_t)gn * K + k0 + lc);
            Bs[lc + 0][r] = bv.x; Bs[lc + 1][r] = bv.y;
            Bs[lc + 2][r] = bv.z; Bs[lc + 3][r] = bv.w;
        }
        __syncthreads();

        #pragma unroll
        for (int k = 0; k < 16; ++k) {
            float ra[8], rb[8];
            *(float4*)&ra[0] = *(const float4*)&As[k][ty * 8];
            *(float4*)&ra[4] = *(const float4*)&As[k][ty * 8 + 4];
            *(float4*)&rb[0] = *(const float4*)&Bs[k][tx * 8];
            *(float4*)&rb[4] = *(const float4*)&Bs[k][tx * 8 + 4];
            #pragma unroll
            for (int i = 0; i < 8; ++i)
                #pragma unroll
                for (int j = 0; j < 8; ++j)
                    acc[i][j] += ra[i] * rb[j];
        }
        __syncthreads();
    }

    #pragma unroll
    for (int i = 0; i < 8; ++i) {
        const int gm = rowBase + ty * 8 + i;
        if (gm >= M) continue;
        #pragma unroll
        for (int j4 = 0; j4 < 2; ++j4) {
            const int gn = colBase + tx * 8 + j4 * 4;
            float4 v;
            v.x = acc[i][j4 * 4 + 0];
            v.y = acc[i][j4 * 4 + 1];
            v.z = acc[i][j4 * 4 + 2];
            v.w = acc[i][j4 * 4 + 3];
            if (bias) {
                v.x += bias[gn + 0]; v.y += bias[gn + 1];
                v.z += bias[gn + 2]; v.w += bias[gn + 3];
            }
            *(float4*)(C + (size_t)gm * N + gn) = v;
        }
    }
}

// ---------------------------------------------------------------------------
// Attention: one CTA per (b, h). K/V resident in smem (stride 65 padding ->
// conflict-free). 8 warps; each warp processes 4 query rows per group,
// 7 key columns per lane. Diagonal LSA mask + softmax fused.
// smem layout (floats):
//   Ks: [0, 12805)   Vs: [12805, 25610)   qs: [25610, 27658)  ps: [27658, 33962)
// ---------------------------------------------------------------------------
#define KS_OFF 0
#define VS_OFF 12805
#define QS_OFF 25610
#define PS_OFF 27658
#define ATTN_SMEM_FLOATS 33962
#define ATTN_SMEM_BYTES  (ATTN_SMEM_FLOATS * 4)

__global__ void __launch_bounds__(256)
attn_kernel(const float* __restrict__ qkv, const float* __restrict__ scale,
            float* __restrict__ outp) {
    extern __shared__ float sm[];
    float* Ks = sm + KS_OFF;
    float* Vs = sm + VS_OFF;
    float* qs = sm + QS_OFF;   // [32 rows][64]
    float* ps = sm + PS_OFF;   // [32 rows][197]

    const int b = blockIdx.y;
    const int h = blockIdx.x;
    const int tid  = threadIdx.x;
    const int w    = tid >> 5;
    const int lane = tid & 31;
    const float sc = scale[h];

    const float* base = qkv + (size_t)b * N_ * C3;

    // Load K and V for this head into smem (coalesced in d)
    for (int idx = tid; idx < N_ * DH_; idx += 256) {
        const int row = idx >> 6;
        const int d   = idx & 63;
        Ks[row * 65 + d] = base[row * C3 +     D_ + h * DH_ + d];
        Vs[row * 65 + d] = base[row * C3 + 2 * D_ + h * DH_ + d];
    }
    __syncthreads();

    for (int g = 0; g < 7; ++g) {
        const int i0 = g * 32 + w * 4;

        // Load 4 q rows for this warp into smem
        #pragma unroll
        for (int r = 0; r < 4; ++r) {
            const int i = i0 + r;
            float v0 = 0.f, v1 = 0.f;
            if (i < N_) {
                v0 = base[i * C3 + h * DH_ + lane];
                v1 = base[i * C3 + h * DH_ + lane + 32];
            }
            qs[(w * 4 + r) * 64 + lane]      = v0;
            qs[(w * 4 + r) * 64 + lane + 32] = v1;
        }
        __syncwarp();

        // Scores: s[r][t] = q_i . k_j, j = lane + 32*t
        float s[4][7];
        #pragma unroll
        for (int r = 0; r < 4; ++r)
            #pragma unroll
            for (int t = 0; t < 7; ++t) s[r][t] = 0.f;

        #pragma unroll 8
        for (int d = 0; d < 64; ++d) {
            float kd[7];
            #pragma unroll
            for (int t = 0; t < 7; ++t)
                kd[t] = Ks[(lane + 32 * t) * 65 + d];
            #pragma unroll
            for (int r = 0; r < 4; ++r) {
                const float qd = qs[(w * 4 + r) * 64 + d];
                #pragma unroll
                for (int t = 0; t < 7; ++t)
                    s[r][t] += qd * kd[t];
            }
        }

        // Scale + LSA diagonal mask + softmax (per row, warp-wide)
        #pragma unroll
        for (int r = 0; r < 4; ++r) {
            const int i = i0 + r;
            float m = -3.0e38f;
            #pragma unroll
            for (int t = 0; t < 7; ++t) {
                const int j = lane + 32 * t;
                float v = s[r][t] * sc;
                if (j == i)   v = MASK_VAL;
                if (j >= N_)  v = -3.0e38f;
                s[r][t] = v;
                m = fmaxf(m, v);
            }
            #pragma unroll
            for (int off = 16; off; off >>= 1)
                m = fmaxf(m, __shfl_xor_sync(0xffffffffu, m, off));
            float sum = 0.f;
            #pragma unroll
            for (int t = 0; t < 7; ++t) {
                const int j = lane + 32 * t;
                const float e = (j < N_) ? __expf(s[r][t] - m) : 0.f;
                s[r][t] = e;
                sum += e;
            }
            #pragma unroll
            for (int off = 16; off; off >>= 1)
                sum += __shfl_xor_sync(0xffffffffu, sum, off);
            const float inv = 1.0f / sum;
            #pragma unroll
            for (int t = 0; t < 7; ++t) {
                const int j = lane + 32 * t;
                if (j < N_) ps[(w * 4 + r) * 197 + j] = s[r][t] * inv;
            }
        }
        __syncwarp();

        // PV: out[i][d] = sum_j p[i][j] * v[j][d]; lane owns d = lane, lane+32
        float acc[4][2];
        #pragma unroll
        for (int r = 0; r < 4; ++r) { acc[r][0] = 0.f; acc[r][1] = 0.f; }

        for (int j = 0; j < N_; ++j) {
            const float v0 = Vs[j * 65 + lane];
            const float v1 = Vs[j * 65 + lane + 32];
            #pragma unroll
            for (int r = 0; r < 4; ++r) {
                const float p = ps[(w * 4 + r) * 197 + j];
                acc[r][0] += p * v0;
                acc[r][1] += p * v1;
            }
        }

        #pragma unroll
        for (int r = 0; r < 4; ++r) {
            const int i = i0 + r;
            if (i < N_) {
                float* o = outp + ((size_t)b * N_ + i) * D_ + h * DH_;
                o[lane]      = acc[r][0];
                o[lane + 32] = acc[r][1];
            }
        }
        __syncwarp();
    }
}

// ---------------------------------------------------------------------------
extern "C" void kernel_launch(void* const* d_in, const int* in_sizes, int n_in,
                              void* d_out, int out_size) {
    const float* x     = (const float*)d_in[0];
    const float* Wqkv  = (const float*)d_in[1];
    const float* scale = (const float*)d_in[2];
    const float* Wout  = (const float*)d_in[3];
    const float* bout  = (const float*)d_in[4];
    float* out = (float*)d_out;

    void* p_qkv  = nullptr;
    void* p_attn = nullptr;
    cudaGetSymbolAddress(&p_qkv,  g_qkv);
    cudaGetSymbolAddress(&p_attn, g_attn);
    float* qkv  = (float*)p_qkv;
    float* attn = (float*)p_attn;

    cudaFuncSetAttribute(attn_kernel,
                         cudaFuncAttributeMaxDynamicSharedMemorySize,
                         ATTN_SMEM_BYTES);

    const int M = B_ * N_;  // 12608

    // 1) qkv = x @ W_qkv^T     [M, 2304]
    {
        dim3 grid(C3 / 128, (M + 127) / 128);
        sgemm_nt<<<grid, 256>>>(x, Wqkv, nullptr, qkv, M, C3, D_);
    }

    // 2) attention per (b, h)  -> attn [M, 768]
    {
        dim3 grid(H_, B_);
        attn_kernel<<<grid, 256, ATTN_SMEM_BYTES>>>(qkv, scale, attn);
    }

    // 3) out = attn @ W_out^T + b_out   [M, 768]
    {
        dim3 grid(D_ / 128, (M + 127) / 128);
        sgemm_nt<<<grid, 256>>>(attn, Wout, bout, out, M, D_, D_);
    }
}

// round 2
// speedup vs baseline: 2.1330x; 2.1330x over previous
#include <cuda_runtime.h>
#include <cstdint>

#define B_  64
#define N_  197
#define D_  768
#define H_  12
#define DH_ 64
#define C3  2304          // 3*H*DH
#define MASK_VAL -987654321.0f

// Scratch buffers (device globals: allocation-free contract)
__device__ float g_qkv [B_ * N_ * C3];   // ~116 MB
__device__ float g_attn[B_ * N_ * D_];   // ~39 MB

// ---------------------------------------------------------------------------
// TF32 tensor-core GEMM (NT): C[m,n] = sum_k A[m,k]*W[n,k] (+ bias[n])
// 128x128x32 CTA tile, 8 warps (2m x 4n), warp tile 64x32,
// mma.sync.m16n8k8.tf32, fp32 accum. Smem [128][36] pad -> conflict-free
// fragment LDS (bank = 4*groupID + tig, a lane bijection) and aligned STS.128.
// ---------------------------------------------------------------------------
__device__ __forceinline__ uint32_t f2tf32(float x) {
    uint32_t r;
    asm("cvt.rna.tf32.f32 %0, %1;" : "=r"(r) : "f"(x));
    return r;
}

__global__ void __launch_bounds__(256, 2)
gemm_tf32(const float* __restrict__ A, const float* __restrict__ W,
          const float* __restrict__ bias, float* __restrict__ C,
          int M, int N, int K) {
    __shared__ float As[128][36];
    __shared__ float Bs[128][36];

    const int tid  = threadIdx.x;
    const int lane = tid & 31;
    const int wid  = tid >> 5;
    const int wm   = wid >> 2;      // 0..1
    const int wn   = wid & 3;       // 0..3
    const int gid  = lane >> 2;     // 0..7  (groupID)
    const int qid  = lane & 3;      // 0..3  (thread-in-group)

    const int rowBase = blockIdx.y * 128;
    const int colBase = blockIdx.x * 128;

    float acc[4][4][4];
    #pragma unroll
    for (int i = 0; i < 4; ++i)
        #pragma unroll
        for (int j = 0; j < 4; ++j)
            #pragma unroll
            for (int r = 0; r < 4; ++r) acc[i][j][r] = 0.0f;

    for (int k0 = 0; k0 < K; k0 += 32) {
        // Global -> smem (tf32-converted), STS.128 aligned, conflict-free
        #pragma unroll
        for (int i = 0; i < 4; ++i) {
            const int fid = tid + i * 256;       // 0..1023
            const int m   = fid >> 3;            // 0..127
            const int c   = (fid & 7) * 4;       // 0,4,..,28
            const int gm  = rowBase + m;
            float4 av = make_float4(0.f, 0.f, 0.f, 0.f);
            if (gm < M) av = *(const float4*)(A + (size_t)gm * K + k0 + c);
            float4 at;
            at.x = __uint_as_float(f2tf32(av.x));
            at.y = __uint_as_float(f2tf32(av.y));
            at.z = __uint_as_float(f2tf32(av.z));
            at.w = __uint_as_float(f2tf32(av.w));
            *(float4*)&As[m][c] = at;

            const int gn = colBase + m;          // N is a multiple of 128
            float4 bv = *(const float4*)(W + (size_t)gn * K + k0 + c);
            float4 bt;
            bt.x = __uint_as_float(f2tf32(bv.x));
            bt.y = __uint_as_float(f2tf32(bv.y));
            bt.z = __uint_as_float(f2tf32(bv.z));
            bt.w = __uint_as_float(f2tf32(bv.w));
            *(float4*)&Bs[m][c] = bt;
        }
        __syncthreads();

        #pragma unroll
        for (int kk = 0; kk < 4; ++kk) {
            const int kb = kk * 8;
            uint32_t af[4][4], bf[4][2];
            #pragma unroll
            for (int mt = 0; mt < 4; ++mt) {
                const int r = wm * 64 + mt * 16 + gid;
                af[mt][0] = __float_as_uint(As[r    ][kb + qid    ]);
                af[mt][1] = __float_as_uint(As[r + 8][kb + qid    ]);
                af[mt][2] = __float_as_uint(As[r    ][kb + qid + 4]);
                af[mt][3] = __float_as_uint(As[r + 8][kb + qid + 4]);
            }
            #pragma unroll
            for (int nt = 0; nt < 4; ++nt) {
                const int cn = wn * 32 + nt * 8 + gid;
                bf[nt][0] = __float_as_uint(Bs[cn][kb + qid    ]);
                bf[nt][1] = __float_as_uint(Bs[cn][kb + qid + 4]);
            }
            #pragma unroll
            for (int mt = 0; mt < 4; ++mt)
                #pragma unroll
                for (int nt = 0; nt < 4; ++nt) {
                    float* c = acc[mt][nt];
                    asm volatile(
                        "mma.sync.aligned.m16n8k8.row.col.f32.tf32.tf32.f32 "
                        "{%0,%1,%2,%3}, {%4,%5,%6,%7}, {%8,%9}, {%0,%1,%2,%3};\n"
                        : "+f"(c[0]), "+f"(c[1]), "+f"(c[2]), "+f"(c[3])
                        : "r"(af[mt][0]), "r"(af[mt][1]),
                          "r"(af[mt][2]), "r"(af[mt][3]),
                          "r"(bf[nt][0]), "r"(bf[nt][1]));
                }
        }
        __syncthreads();
    }

    // Epilogue: c0,c1 = (row, 2q), (row, 2q+1); c2,c3 = row+8
    #pragma unroll
    for (int mt = 0; mt < 4; ++mt) {
        #pragma unroll
        for (int nt = 0; nt < 4; ++nt) {
            const int r0 = rowBase + wm * 64 + mt * 16 + gid;
            const int cc = colBase + wn * 32 + nt * 8 + qid * 2;
            float bx = 0.f, by = 0.f;
            if (bias) { bx = bias[cc]; by = bias[cc + 1]; }
            if (r0 < M) {
                float2 v = make_float2(acc[mt][nt][0] + bx, acc[mt][nt][1] + by);
                *(float2*)(C + (size_t)r0 * N + cc) = v;
            }
            const int r1 = r0 + 8;
            if (r1 < M) {
                float2 v = make_float2(acc[mt][nt][2] + bx, acc[mt][nt][3] + by);
                *(float2*)(C + (size_t)r1 * N + cc) = v;
            }
        }
    }
}

// ---------------------------------------------------------------------------
// Attention: one CTA per (b, h). K/V resident in smem (stride 65 padding ->
// conflict-free). 8 warps; each warp processes 4 query rows per group,
// 7 key columns per lane. Diagonal LSA mask + softmax fused.
// ---------------------------------------------------------------------------
#define KS_OFF 0
#define VS_OFF 12805
#define QS_OFF 25610
#define PS_OFF 27658
#define ATTN_SMEM_FLOATS 33962
#define ATTN_SMEM_BYTES  (ATTN_SMEM_FLOATS * 4)

__global__ void __launch_bounds__(256)
attn_kernel(const float* __restrict__ qkv, const float* __restrict__ scale,
            float* __restrict__ outp) {
    extern __shared__ float sm[];
    float* Ks = sm + KS_OFF;
    float* Vs = sm + VS_OFF;
    float* qs = sm + QS_OFF;   // [32 rows][64]
    float* ps = sm + PS_OFF;   // [32 rows][197]

    const int b = blockIdx.y;
    const int h = blockIdx.x;
    const int tid  = threadIdx.x;
    const int w    = tid >> 5;
    const int lane = tid & 31;
    const float sc = scale[h];

    const float* base = qkv + (size_t)b * N_ * C3;

    for (int idx = tid; idx < N_ * DH_; idx += 256) {
        const int row = idx >> 6;
        const int d   = idx & 63;
        Ks[row * 65 + d] = base[row * C3 +     D_ + h * DH_ + d];
        Vs[row * 65 + d] = base[row * C3 + 2 * D_ + h * DH_ + d];
    }
    __syncthreads();

    for (int g = 0; g < 7; ++g) {
        const int i0 = g * 32 + w * 4;

        #pragma unroll
        for (int r = 0; r < 4; ++r) {
            const int i = i0 + r;
            float v0 = 0.f, v1 = 0.f;
            if (i < N_) {
                v0 = base[i * C3 + h * DH_ + lane];
                v1 = base[i * C3 + h * DH_ + lane + 32];
            }
            qs[(w * 4 + r) * 64 + lane]      = v0;
            qs[(w * 4 + r) * 64 + lane + 32] = v1;
        }
        __syncwarp();

        float s[4][7];
        #pragma unroll
        for (int r = 0; r < 4; ++r)
            #pragma unroll
            for (int t = 0; t < 7; ++t) s[r][t] = 0.f;

        #pragma unroll 8
        for (int d = 0; d < 64; ++d) {
            float kd[7];
            #pragma unroll
            for (int t = 0; t < 7; ++t)
                kd[t] = Ks[(lane + 32 * t) * 65 + d];
            #pragma unroll
            for (int r = 0; r < 4; ++r) {
                const float qd = qs[(w * 4 + r) * 64 + d];
                #pragma unroll
                for (int t = 0; t < 7; ++t)
                    s[r][t] += qd * kd[t];
            }
        }

        #pragma unroll
        for (int r = 0; r < 4; ++r) {
            const int i = i0 + r;
            float m = -3.0e38f;
            #pragma unroll
            for (int t = 0; t < 7; ++t) {
                const int j = lane + 32 * t;
                float v = s[r][t] * sc;
                if (j == i)   v = MASK_VAL;
                if (j >= N_)  v = -3.0e38f;
                s[r][t] = v;
                m = fmaxf(m, v);
            }
            #pragma unroll
            for (int off = 16; off; off >>= 1)
                m = fmaxf(m, __shfl_xor_sync(0xffffffffu, m, off));
            float sum = 0.f;
            #pragma unroll
            for (int t = 0; t < 7; ++t) {
                const int j = lane + 32 * t;
                const float e = (j < N_) ? __expf(s[r][t] - m) : 0.f;
                s[r][t] = e;
                sum += e;
            }
            #pragma unroll
            for (int off = 16; off; off >>= 1)
                sum += __shfl_xor_sync(0xffffffffu, sum, off);
            const float inv = 1.0f / sum;
            #pragma unroll
            for (int t = 0; t < 7; ++t) {
                const int j = lane + 32 * t;
                if (j < N_) ps[(w * 4 + r) * 197 + j] = s[r][t] * inv;
            }
        }
        __syncwarp();

        float acc[4][2];
        #pragma unroll
        for (int r = 0; r < 4; ++r) { acc[r][0] = 0.f; acc[r][1] = 0.f; }

        for (int j = 0; j < N_; ++j) {
            const float v0 = Vs[j * 65 + lane];
            const float v1 = Vs[j * 65 + lane + 32];
            #pragma unroll
            for (int r = 0; r < 4; ++r) {
                const float p = ps[(w * 4 + r) * 197 + j];
                acc[r][0] += p * v0;
                acc[r][1] += p * v1;
            }
        }

        #pragma unroll
        for (int r = 0; r < 4; ++r) {
            const int i = i0 + r;
            if (i < N_) {
                float* o = outp + ((size_t)b * N_ + i) * D_ + h * DH_;
                o[lane]      = acc[r][0];
                o[lane + 32] = acc[r][1];
            }
        }
        __syncwarp();
    }
}

// ---------------------------------------------------------------------------
extern "C" void kernel_launch(void* const* d_in, const int* in_sizes, int n_in,
                              void* d_out, int out_size) {
    const float* x     = (const float*)d_in[0];
    const float* Wqkv  = (const float*)d_in[1];
    const float* scale = (const float*)d_in[2];
    const float* Wout  = (const float*)d_in[3];
    const float* bout  = (const float*)d_in[4];
    float* out = (float*)d_out;

    void* p_qkv  = nullptr;
    void* p_attn = nullptr;
    cudaGetSymbolAddress(&p_qkv,  g_qkv);
    cudaGetSymbolAddress(&p_attn, g_attn);
    float* qkv  = (float*)p_qkv;
    float* attn = (float*)p_attn;

    cudaFuncSetAttribute(attn_kernel,
                         cudaFuncAttributeMaxDynamicSharedMemorySize,
                         ATTN_SMEM_BYTES);

    const int M = B_ * N_;  // 12608

    // 1) qkv = x @ W_qkv^T     [M, 2304]
    {
        dim3 grid(C3 / 128, (M + 127) / 128);
        gemm_tf32<<<grid, 256>>>(x, Wqkv, nullptr, qkv, M, C3, D_);
    }

    // 2) attention per (b, h)  -> attn [M, 768]
    {
        dim3 grid(H_, B_);
        attn_kernel<<<grid, 256, ATTN_SMEM_BYTES>>>(qkv, scale, attn);
    }

    // 3) out = attn @ W_out^T + b_out   [M, 768]
    {
        dim3 grid(D_ / 128, (M + 127) / 128);
        gemm_tf32<<<grid, 256>>>(attn, Wout, bout, out, M, D_, D_);
    }
}

// round 3
// speedup vs baseline: 3.1297x; 1.4673x over previous
#include <cuda_runtime.h>
#include <cstdint>

#define B_  64
#define N_  197
#define D_  768
#define H_  12
#define DH_ 64
#define C3  2304          // 3*H*DH
#define MASK_VAL -987654321.0f

#define NP  208           // padded seq len (13 * 16)
#define SKV 72            // smem row stride for Q/K/V (bank bijection for PV B-frags)

// Scratch buffers (device globals: allocation-free contract)
__device__ float g_qkv [B_ * N_ * C3];   // ~116 MB
__device__ float g_attn[B_ * N_ * D_];   // ~39 MB

__device__ __forceinline__ uint32_t f2tf32(float x) {
    uint32_t r;
    asm("cvt.rna.tf32.f32 %0, %1;" : "=r"(r) : "f"(x));
    return r;
}

__device__ __forceinline__ void mma_tf32(float c[4],
                                         uint32_t a0, uint32_t a1,
                                         uint32_t a2, uint32_t a3,
                                         uint32_t b0, uint32_t b1) {
    asm volatile(
        "mma.sync.aligned.m16n8k8.row.col.f32.tf32.tf32.f32 "
        "{%0,%1,%2,%3}, {%4,%5,%6,%7}, {%8,%9}, {%0,%1,%2,%3};\n"
        : "+f"(c[0]), "+f"(c[1]), "+f"(c[2]), "+f"(c[3])
        : "r"(a0), "r"(a1), "r"(a2), "r"(a3), "r"(b0), "r"(b1));
}

// ---------------------------------------------------------------------------
// TF32 tensor-core GEMM (NT): C[m,n] = sum_k A[m,k]*W[n,k] (+ bias[n])
// ---------------------------------------------------------------------------
__global__ void __launch_bounds__(256, 2)
gemm_tf32(const float* __restrict__ A, const float* __restrict__ W,
          const float* __restrict__ bias, float* __restrict__ C,
          int M, int N, int K) {
    __shared__ float As[128][36];
    __shared__ float Bs[128][36];

    const int tid  = threadIdx.x;
    const int lane = tid & 31;
    const int wid  = tid >> 5;
    const int wm   = wid >> 2;
    const int wn   = wid & 3;
    const int gid  = lane >> 2;
    const int qid  = lane & 3;

    const int rowBase = blockIdx.y * 128;
    const int colBase = blockIdx.x * 128;

    float acc[4][4][4];
    #pragma unroll
    for (int i = 0; i < 4; ++i)
        #pragma unroll
        for (int j = 0; j < 4; ++j)
            #pragma unroll
            for (int r = 0; r < 4; ++r) acc[i][j][r] = 0.0f;

    for (int k0 = 0; k0 < K; k0 += 32) {
        #pragma unroll
        for (int i = 0; i < 4; ++i) {
            const int fid = tid + i * 256;
            const int m   = fid >> 3;
            const int c   = (fid & 7) * 4;
            const int gm  = rowBase + m;
            float4 av = make_float4(0.f, 0.f, 0.f, 0.f);
            if (gm < M) av = *(const float4*)(A + (size_t)gm * K + k0 + c);
            float4 at;
            at.x = __uint_as_float(f2tf32(av.x));
            at.y = __uint_as_float(f2tf32(av.y));
            at.z = __uint_as_float(f2tf32(av.z));
            at.w = __uint_as_float(f2tf32(av.w));
            *(float4*)&As[m][c] = at;

            const int gn = colBase + m;
            float4 bv = *(const float4*)(W + (size_t)gn * K + k0 + c);
            float4 bt;
            bt.x = __uint_as_float(f2tf32(bv.x));
            bt.y = __uint_as_float(f2tf32(bv.y));
            bt.z = __uint_as_float(f2tf32(bv.z));
            bt.w = __uint_as_float(f2tf32(bv.w));
            *(float4*)&Bs[m][c] = bt;
        }
        __syncthreads();

        #pragma unroll
        for (int kk = 0; kk < 4; ++kk) {
            const int kb = kk * 8;
            uint32_t af[4][4], bf[4][2];
            #pragma unroll
            for (int mt = 0; mt < 4; ++mt) {
                const int r = wm * 64 + mt * 16 + gid;
                af[mt][0] = __float_as_uint(As[r    ][kb + qid    ]);
                af[mt][1] = __float_as_uint(As[r + 8][kb + qid    ]);
                af[mt][2] = __float_as_uint(As[r    ][kb + qid + 4]);
                af[mt][3] = __float_as_uint(As[r + 8][kb + qid + 4]);
            }
            #pragma unroll
            for (int nt = 0; nt < 4; ++nt) {
                const int cn = wn * 32 + nt * 8 + gid;
                bf[nt][0] = __float_as_uint(Bs[cn][kb + qid    ]);
                bf[nt][1] = __float_as_uint(Bs[cn][kb + qid + 4]);
            }
            #pragma unroll
            for (int mt = 0; mt < 4; ++mt)
                #pragma unroll
                for (int nt = 0; nt < 4; ++nt)
                    mma_tf32(acc[mt][nt], af[mt][0], af[mt][1], af[mt][2],
                             af[mt][3], bf[nt][0], bf[nt][1]);
        }
        __syncthreads();
    }

    #pragma unroll
    for (int mt = 0; mt < 4; ++mt) {
        #pragma unroll
        for (int nt = 0; nt < 4; ++nt) {
            const int r0 = rowBase + wm * 64 + mt * 16 + gid;
            const int cc = colBase + wn * 32 + nt * 8 + qid * 2;
            float bx = 0.f, by = 0.f;
            if (bias) { bx = bias[cc]; by = bias[cc + 1]; }
            if (r0 < M) {
                float2 v = make_float2(acc[mt][nt][0] + bx, acc[mt][nt][1] + by);
                *(float2*)(C + (size_t)r0 * N + cc) = v;
            }
            const int r1 = r0 + 8;
            if (r1 < M) {
                float2 v = make_float2(acc[mt][nt][2] + bx, acc[mt][nt][3] + by);
                *(float2*)(C + (size_t)r1 * N + cc) = v;
            }
        }
    }
}

// ---------------------------------------------------------------------------
// Tensor-core attention: one CTA per (b, h).
// Q/K/V staged in smem as tf32 [NP][SKV]. Each warp owns 16-row query chunks.
// S chunk in accumulators (26 n-tiles), in-register mask + softmax with quad
// shuffles, accumulator->A-fragment transpose via shuffles, PV mma -> output.
// ---------------------------------------------------------------------------
#define ATTN_SMEM_BYTES (3 * NP * SKV * 4)   // 179712

__global__ void __launch_bounds__(256)
attn_mma(const float* __restrict__ qkv, const float* __restrict__ scale,
         float* __restrict__ outp) {
    extern __shared__ float sm[];
    float* Qs = sm;
    float* Ks = sm + NP * SKV;
    float* Vs = sm + 2 * NP * SKV;

    const int b = blockIdx.y;
    const int h = blockIdx.x;
    const int tid  = threadIdx.x;
    const int w    = tid >> 5;
    const int lane = tid & 31;
    const int gid  = lane >> 2;   // groupID (row within fragment)
    const int qid  = lane & 3;    // thread-in-group
    const float sc = scale[h];

    const float* base = qkv + (size_t)b * N_ * C3 + h * DH_;

    // Stage Q (pre-scaled), K, V as tf32; zero pad rows 197..207
    for (int idx = tid; idx < NP * DH_; idx += 256) {
        const int row = idx >> 6;
        const int d   = idx & 63;
        float q = 0.f, k = 0.f, v = 0.f;
        if (row < N_) {
            const float* p = base + (size_t)row * C3 + d;
            q = p[0] * sc;
            k = p[D_];
            v = p[2 * D_];
        }
        Qs[row * SKV + d] = __uint_as_float(f2tf32(q));
        Ks[row * SKV + d] = __uint_as_float(f2tf32(k));
        Vs[row * SKV + d] = __uint_as_float(f2tf32(v));
    }
    __syncthreads();

    for (int c = w; c < 13; c += 8) {
        const int m0 = c * 16;
        const int r_lo = m0 + gid;
        const int r_hi = r_lo + 8;

        // ---- S = Q K^T (chunk rows m0..m0+15, all 208 cols) ----
        float s[26][4];
        #pragma unroll
        for (int nt = 0; nt < 26; ++nt)
            #pragma unroll
            for (int i = 0; i < 4; ++i) s[nt][i] = 0.f;

        #pragma unroll
        for (int kt = 0; kt < 8; ++kt) {
            const int kb = kt * 8;
            const uint32_t a0 = __float_as_uint(Qs[r_lo * SKV + kb + qid    ]);
            const uint32_t a1 = __float_as_uint(Qs[r_hi * SKV + kb + qid    ]);
            const uint32_t a2 = __float_as_uint(Qs[r_lo * SKV + kb + qid + 4]);
            const uint32_t a3 = __float_as_uint(Qs[r_hi * SKV + kb + qid + 4]);
            #pragma unroll
            for (int nt = 0; nt < 26; ++nt) {
                const uint32_t b0 =
                    __float_as_uint(Ks[(nt * 8 + gid) * SKV + kb + qid    ]);
                const uint32_t b1 =
                    __float_as_uint(Ks[(nt * 8 + gid) * SKV + kb + qid + 4]);
                mma_tf32(s[nt], a0, a1, a2, a3, b0, b1);
            }
        }

        // ---- mask + softmax in accumulator layout ----
        float mx_lo = -3.0e38f, mx_hi = -3.0e38f;
        #pragma unroll
        for (int nt = 0; nt < 26; ++nt) {
            const int j0 = nt * 8 + 2 * qid;
            const int j1 = j0 + 1;
            float v0 = s[nt][0], v1 = s[nt][1], v2 = s[nt][2], v3 = s[nt][3];
            v0 = (j0 >= N_) ? -3.0e38f : ((j0 == r_lo) ? MASK_VAL : v0);
            v1 = (j1 >= N_) ? -3.0e38f : ((j1 == r_lo) ? MASK_VAL : v1);
            v2 = (j0 >= N_) ? -3.0e38f : ((j0 == r_hi) ? MASK_VAL : v2);
            v3 = (j1 >= N_) ? -3.0e38f : ((j1 == r_hi) ? MASK_VAL : v3);
            s[nt][0] = v0; s[nt][1] = v1; s[nt][2] = v2; s[nt][3] = v3;
            mx_lo = fmaxf(mx_lo, fmaxf(v0, v1));
            mx_hi = fmaxf(mx_hi, fmaxf(v2, v3));
        }
        mx_lo = fmaxf(mx_lo, __shfl_xor_sync(0xffffffffu, mx_lo, 1));
        mx_lo = fmaxf(mx_lo, __shfl_xor_sync(0xffffffffu, mx_lo, 2));
        mx_hi = fmaxf(mx_hi, __shfl_xor_sync(0xffffffffu, mx_hi, 1));
        mx_hi = fmaxf(mx_hi, __shfl_xor_sync(0xffffffffu, mx_hi, 2));

        float sum_lo = 0.f, sum_hi = 0.f;
        #pragma unroll
        for (int nt = 0; nt < 26; ++nt) {
            float e0 = __expf(s[nt][0] - mx_lo);
            float e1 = __expf(s[nt][1] - mx_lo);
            float e2 = __expf(s[nt][2] - mx_hi);
            float e3 = __expf(s[nt][3] - mx_hi);
            s[nt][0] = e0; s[nt][1] = e1; s[nt][2] = e2; s[nt][3] = e3;
            sum_lo += e0 + e1;
            sum_hi += e2 + e3;
        }
        sum_lo += __shfl_xor_sync(0xffffffffu, sum_lo, 1);
        sum_lo += __shfl_xor_sync(0xffffffffu, sum_lo, 2);
        sum_hi += __shfl_xor_sync(0xffffffffu, sum_hi, 1);
        sum_hi += __shfl_xor_sync(0xffffffffu, sum_hi, 2);
        const float inv_lo = 1.0f / sum_lo;
        const float inv_hi = 1.0f / sum_hi;
        #pragma unroll
        for (int nt = 0; nt < 26; ++nt) {
            s[nt][0] = __uint_as_float(f2tf32(s[nt][0] * inv_lo));
            s[nt][1] = __uint_as_float(f2tf32(s[nt][1] * inv_lo));
            s[nt][2] = __uint_as_float(f2tf32(s[nt][2] * inv_hi));
            s[nt][3] = __uint_as_float(f2tf32(s[nt][3] * inv_hi));
        }

        // ---- O = P V (k over 208 cols of P, n over 64 head dims) ----
        float o[8][4];
        #pragma unroll
        for (int nt = 0; nt < 8; ++nt)
            #pragma unroll
            for (int i = 0; i < 4; ++i) o[nt][i] = 0.f;

        const int srcA = (gid << 2) | (qid >> 1);
        const int srcB = srcA + 2;
        const bool odd = (qid & 1);

        #pragma unroll
        for (int kt = 0; kt < 26; ++kt) {
            // accumulator -> A-fragment transpose via shuffles
            float lo, hi;
            lo = __shfl_sync(0xffffffffu, s[kt][0], srcA);
            hi = __shfl_sync(0xffffffffu, s[kt][1], srcA);
            const uint32_t a0 = __float_as_uint(odd ? hi : lo);
            lo = __shfl_sync(0xffffffffu, s[kt][2], srcA);
            hi = __shfl_sync(0xffffffffu, s[kt][3], srcA);
            const uint32_t a1 = __float_as_uint(odd ? hi : lo);
            lo = __shfl_sync(0xffffffffu, s[kt][0], srcB);
            hi = __shfl_sync(0xffffffffu, s[kt][1], srcB);
            const uint32_t a2 = __float_as_uint(odd ? hi : lo);
            lo = __shfl_sync(0xffffffffu, s[kt][2], srcB);
            hi = __shfl_sync(0xffffffffu, s[kt][3], srcB);
            const uint32_t a3 = __float_as_uint(odd ? hi : lo);

            const int kb = kt * 8;
            #pragma unroll
            for (int nt = 0; nt < 8; ++nt) {
                const uint32_t b0 =
                    __float_as_uint(Vs[(kb + qid    ) * SKV + nt * 8 + gid]);
                const uint32_t b1 =
                    __float_as_uint(Vs[(kb + qid + 4) * SKV + nt * 8 + gid]);
                mma_tf32(o[nt], a0, a1, a2, a3, b0, b1);
            }
        }

        // ---- store chunk output ----
        #pragma unroll
        for (int nt = 0; nt < 8; ++nt) {
            const int cc = h * DH_ + nt * 8 + 2 * qid;
            if (r_lo < N_) {
                *(float2*)(outp + ((size_t)b * N_ + r_lo) * D_ + cc) =
                    make_float2(o[nt][0], o[nt][1]);
            }
            if (r_hi < N_) {
                *(float2*)(outp + ((size_t)b * N_ + r_hi) * D_ + cc) =
                    make_float2(o[nt][2], o[nt][3]);
            }
        }
    }
}

// ---------------------------------------------------------------------------
extern "C" void kernel_launch(void* const* d_in, const int* in_sizes, int n_in,
                              void* d_out, int out_size) {
    const float* x     = (const float*)d_in[0];
    const float* Wqkv  = (const float*)d_in[1];
    const float* scale = (const float*)d_in[2];
    const float* Wout  = (const float*)d_in[3];
    const float* bout  = (const float*)d_in[4];
    float* out = (float*)d_out;

    void* p_qkv  = nullptr;
    void* p_attn = nullptr;
    cudaGetSymbolAddress(&p_qkv,  g_qkv);
    cudaGetSymbolAddress(&p_attn, g_attn);
    float* qkv  = (float*)p_qkv;
    float* attn = (float*)p_attn;

    cudaFuncSetAttribute(attn_mma,
                         cudaFuncAttributeMaxDynamicSharedMemorySize,
                         ATTN_SMEM_BYTES);

    const int M = B_ * N_;  // 12608

    // 1) qkv = x @ W_qkv^T     [M, 2304]
    {
        dim3 grid(C3 / 128, (M + 127) / 128);
        gemm_tf32<<<grid, 256>>>(x, Wqkv, nullptr, qkv, M, C3, D_);
    }

    // 2) attention per (b, h)  -> attn [M, 768]
    {
        dim3 grid(H_, B_);
        attn_mma<<<grid, 256, ATTN_SMEM_BYTES>>>(qkv, scale, attn);
    }

    // 3) out = attn @ W_out^T + b_out   [M, 768]
    {
        dim3 grid(D_ / 128, (M + 127) / 128);
        gemm_tf32<<<grid, 256>>>(attn, Wout, bout, out, M, D_, D_);
    }
}

// round 4
// speedup vs baseline: 3.3374x; 1.0664x over previous
#include <cuda_runtime.h>
#include <cstdint>

#define B_  64
#define N_  197
#define D_  768
#define H_  12
#define DH_ 64
#define C3  2304          // 3*H*DH
#define MASK_VAL -987654321.0f

#define NP  208           // padded seq len (13 * 16)
#define SKV 72            // smem row stride for Q/K/V

// Scratch buffers (device globals: allocation-free contract)
__device__ float g_qkv [B_ * N_ * C3];   // ~116 MB
__device__ float g_attn[B_ * N_ * D_];   // ~39 MB

__device__ __forceinline__ uint32_t f2tf32(float x) {
    uint32_t r;
    asm("cvt.rna.tf32.f32 %0, %1;" : "=r"(r) : "f"(x));
    return r;
}

__device__ __forceinline__ uint32_t ld_tf32(const float* p) {
    return f2tf32(*p);
}

__device__ __forceinline__ void mma_tf32(float c[4],
                                         uint32_t a0, uint32_t a1,
                                         uint32_t a2, uint32_t a3,
                                         uint32_t b0, uint32_t b1) {
    asm volatile(
        "mma.sync.aligned.m16n8k8.row.col.f32.tf32.tf32.f32 "
        "{%0,%1,%2,%3}, {%4,%5,%6,%7}, {%8,%9}, {%0,%1,%2,%3};\n"
        : "+f"(c[0]), "+f"(c[1]), "+f"(c[2]), "+f"(c[3])
        : "r"(a0), "r"(a1), "r"(a2), "r"(a3), "r"(b0), "r"(b1));
}

__device__ __forceinline__ void cp_async16(float* smem_dst, const float* gsrc,
                                           bool pred) {
    uint32_t saddr = (uint32_t)__cvta_generic_to_shared(smem_dst);
    int sz = pred ? 16 : 0;
    asm volatile("cp.async.ca.shared.global [%0], [%1], 16, %2;\n"
                 :: "r"(saddr), "l"(gsrc), "r"(sz));
}
__device__ __forceinline__ void cp_commit() {
    asm volatile("cp.async.commit_group;\n");
}
__device__ __forceinline__ void cp_wait0() {
    asm volatile("cp.async.wait_group 0;\n");
}

// ---------------------------------------------------------------------------
// TF32 tensor-core GEMM (NT), cp.async double-buffered:
// C[m,n] = sum_k A[m,k]*W[n,k] (+ bias[n])
// 128x128x32 CTA tile, 8 warps (2m x 4n). Smem raw fp32 [128][36] per buffer,
// tf32 cvt at fragment load. One __syncthreads per k-tile.
// ---------------------------------------------------------------------------
#define GEMM_BUF_FLOATS (128 * 36)                 // 4608
#define GEMM_SMEM_BYTES (4 * GEMM_BUF_FLOATS * 4)  // 73728

__global__ void __launch_bounds__(256, 2)
gemm_tf32(const float* __restrict__ A, const float* __restrict__ W,
          const float* __restrict__ bias, float* __restrict__ C,
          int M, int N, int K) {
    extern __shared__ float sm[];
    // As buffers at 0, 4608; Bs buffers at 9216, 13824 (floats)

    const int tid  = threadIdx.x;
    const int lane = tid & 31;
    const int wid  = tid >> 5;
    const int wm   = wid >> 2;
    const int wn   = wid & 3;
    const int gid  = lane >> 2;
    const int qid  = lane & 3;

    const int rowBase = blockIdx.y * 128;
    const int colBase = blockIdx.x * 128;

    const int m_ld = tid >> 3;            // 0..31? no: tid/8 -> 0..31 (with i loop covers 128)
    const int c_ld = (tid & 7) * 4;

    float acc[4][4][4];
    #pragma unroll
    for (int i = 0; i < 4; ++i)
        #pragma unroll
        for (int j = 0; j < 4; ++j)
            #pragma unroll
            for (int r = 0; r < 4; ++r) acc[i][j][r] = 0.0f;

    const int nTiles = K >> 5;            // K/32

    // Prefetch tile 0 into buffer 0
    {
        float* sA = sm;
        float* sB = sm + 2 * GEMM_BUF_FLOATS;
        #pragma unroll
        for (int i = 0; i < 4; ++i) {
            const int m  = m_ld + i * 32;
            const int gm = rowBase + m;
            cp_async16(sA + m * 36 + c_ld, A + (size_t)gm * K + c_ld, gm < M);
            const int gn = colBase + m;
            cp_async16(sB + m * 36 + c_ld, W + (size_t)gn * K + c_ld, true);
        }
        cp_commit();
    }

    for (int t = 0; t < nTiles; ++t) {
        cp_wait0();
        __syncthreads();

        if (t + 1 < nTiles) {
            const int k0 = (t + 1) << 5;
            float* sA = sm + ((t + 1) & 1) * GEMM_BUF_FLOATS;
            float* sB = sm + 2 * GEMM_BUF_FLOATS + ((t + 1) & 1) * GEMM_BUF_FLOATS;
            #pragma unroll
            for (int i = 0; i < 4; ++i) {
                const int m  = m_ld + i * 32;
                const int gm = rowBase + m;
                cp_async16(sA + m * 36 + c_ld, A + (size_t)gm * K + k0 + c_ld,
                           gm < M);
                const int gn = colBase + m;
                cp_async16(sB + m * 36 + c_ld, W + (size_t)gn * K + k0 + c_ld,
                           true);
            }
            cp_commit();
        }

        const float* As = sm + (t & 1) * GEMM_BUF_FLOATS;
        const float* Bs = sm + 2 * GEMM_BUF_FLOATS + (t & 1) * GEMM_BUF_FLOATS;

        #pragma unroll
        for (int kk = 0; kk < 4; ++kk) {
            const int kb = kk * 8;
            uint32_t af[4][4], bf[4][2];
            #pragma unroll
            for (int mt = 0; mt < 4; ++mt) {
                const int r = wm * 64 + mt * 16 + gid;
                af[mt][0] = ld_tf32(As + (r    ) * 36 + kb + qid    );
                af[mt][1] = ld_tf32(As + (r + 8) * 36 + kb + qid    );
                af[mt][2] = ld_tf32(As + (r    ) * 36 + kb + qid + 4);
                af[mt][3] = ld_tf32(As + (r + 8) * 36 + kb + qid + 4);
            }
            #pragma unroll
            for (int nt = 0; nt < 4; ++nt) {
                const int cn = wn * 32 + nt * 8 + gid;
                bf[nt][0] = ld_tf32(Bs + cn * 36 + kb + qid    );
                bf[nt][1] = ld_tf32(Bs + cn * 36 + kb + qid + 4);
            }
            #pragma unroll
            for (int mt = 0; mt < 4; ++mt)
                #pragma unroll
                for (int nt = 0; nt < 4; ++nt)
                    mma_tf32(acc[mt][nt], af[mt][0], af[mt][1], af[mt][2],
                             af[mt][3], bf[nt][0], bf[nt][1]);
        }
        __syncthreads();
    }

    #pragma unroll
    for (int mt = 0; mt < 4; ++mt) {
        #pragma unroll
        for (int nt = 0; nt < 4; ++nt) {
            const int r0 = rowBase + wm * 64 + mt * 16 + gid;
            const int cc = colBase + wn * 32 + nt * 8 + qid * 2;
            float bx = 0.f, by = 0.f;
            if (bias) { bx = bias[cc]; by = bias[cc + 1]; }
            if (r0 < M) {
                float2 v = make_float2(acc[mt][nt][0] + bx, acc[mt][nt][1] + by);
                *(float2*)(C + (size_t)r0 * N + cc) = v;
            }
            const int r1 = r0 + 8;
            if (r1 < M) {
                float2 v = make_float2(acc[mt][nt][2] + bx, acc[mt][nt][3] + by);
                *(float2*)(C + (size_t)r1 * N + cc) = v;
            }
        }
    }
}

// ---------------------------------------------------------------------------
// Tensor-core attention: one CTA per (b, h).  (unchanged from round 3)
// ---------------------------------------------------------------------------
#define ATTN_SMEM_BYTES (3 * NP * SKV * 4)   // 179712

__global__ void __launch_bounds__(256)
attn_mma(const float* __restrict__ qkv, const float* __restrict__ scale,
         float* __restrict__ outp) {
    extern __shared__ float sm[];
    float* Qs = sm;
    float* Ks = sm + NP * SKV;
    float* Vs = sm + 2 * NP * SKV;

    const int b = blockIdx.y;
    const int h = blockIdx.x;
    const int tid  = threadIdx.x;
    const int w    = tid >> 5;
    const int lane = tid & 31;
    const int gid  = lane >> 2;
    const int qid  = lane & 3;
    const float sc = scale[h];

    const float* base = qkv + (size_t)b * N_ * C3 + h * DH_;

    for (int idx = tid; idx < NP * DH_; idx += 256) {
        const int row = idx >> 6;
        const int d   = idx & 63;
        float q = 0.f, k = 0.f, v = 0.f;
        if (row < N_) {
            const float* p = base + (size_t)row * C3 + d;
            q = p[0] * sc;
            k = p[D_];
            v = p[2 * D_];
        }
        Qs[row * SKV + d] = __uint_as_float(f2tf32(q));
        Ks[row * SKV + d] = __uint_as_float(f2tf32(k));
        Vs[row * SKV + d] = __uint_as_float(f2tf32(v));
    }
    __syncthreads();

    for (int c = w; c < 13; c += 8) {
        const int m0 = c * 16;
        const int r_lo = m0 + gid;
        const int r_hi = r_lo + 8;

        float s[26][4];
        #pragma unroll
        for (int nt = 0; nt < 26; ++nt)
            #pragma unroll
            for (int i = 0; i < 4; ++i) s[nt][i] = 0.f;

        #pragma unroll
        for (int kt = 0; kt < 8; ++kt) {
            const int kb = kt * 8;
            const uint32_t a0 = __float_as_uint(Qs[r_lo * SKV + kb + qid    ]);
            const uint32_t a1 = __float_as_uint(Qs[r_hi * SKV + kb + qid    ]);
            const uint32_t a2 = __float_as_uint(Qs[r_lo * SKV + kb + qid + 4]);
            const uint32_t a3 = __float_as_uint(Qs[r_hi * SKV + kb + qid + 4]);
            #pragma unroll
            for (int nt = 0; nt < 26; ++nt) {
                const uint32_t b0 =
                    __float_as_uint(Ks[(nt * 8 + gid) * SKV + kb + qid    ]);
                const uint32_t b1 =
                    __float_as_uint(Ks[(nt * 8 + gid) * SKV + kb + qid + 4]);
                mma_tf32(s[nt], a0, a1, a2, a3, b0, b1);
            }
        }

        float mx_lo = -3.0e38f, mx_hi = -3.0e38f;
        #pragma unroll
        for (int nt = 0; nt < 26; ++nt) {
            const int j0 = nt * 8 + 2 * qid;
            const int j1 = j0 + 1;
            float v0 = s[nt][0], v1 = s[nt][1], v2 = s[nt][2], v3 = s[nt][3];
            v0 = (j0 >= N_) ? -3.0e38f : ((j0 == r_lo) ? MASK_VAL : v0);
            v1 = (j1 >= N_) ? -3.0e38f : ((j1 == r_lo) ? MASK_VAL : v1);
            v2 = (j0 >= N_) ? -3.0e38f : ((j0 == r_hi) ? MASK_VAL : v2);
            v3 = (j1 >= N_) ? -3.0e38f : ((j1 == r_hi) ? MASK_VAL : v3);
            s[nt][0] = v0; s[nt][1] = v1; s[nt][2] = v2; s[nt][3] = v3;
            mx_lo = fmaxf(mx_lo, fmaxf(v0, v1));
            mx_hi = fmaxf(mx_hi, fmaxf(v2, v3));
        }
        mx_lo = fmaxf(mx_lo, __shfl_xor_sync(0xffffffffu, mx_lo, 1));
        mx_lo = fmaxf(mx_lo, __shfl_xor_sync(0xffffffffu, mx_lo, 2));
        mx_hi = fmaxf(mx_hi, __shfl_xor_sync(0xffffffffu, mx_hi, 1));
        mx_hi = fmaxf(mx_hi, __shfl_xor_sync(0xffffffffu, mx_hi, 2));

        float sum_lo = 0.f, sum_hi = 0.f;
        #pragma unroll
        for (int nt = 0; nt < 26; ++nt) {
            float e0 = __expf(s[nt][0] - mx_lo);
            float e1 = __expf(s[nt][1] - mx_lo);
            float e2 = __expf(s[nt][2] - mx_hi);
            float e3 = __expf(s[nt][3] - mx_hi);
            s[nt][0] = e0; s[nt][1] = e1; s[nt][2] = e2; s[nt][3] = e3;
            sum_lo += e0 + e1;
            sum_hi += e2 + e3;
        }
        sum_lo += __shfl_xor_sync(0xffffffffu, sum_lo, 1);
        sum_lo += __shfl_xor_sync(0xffffffffu, sum_lo, 2);
        sum_hi += __shfl_xor_sync(0xffffffffu, sum_hi, 1);
        sum_hi += __shfl_xor_sync(0xffffffffu, sum_hi, 2);
        const float inv_lo = 1.0f / sum_lo;
        const float inv_hi = 1.0f / sum_hi;
        #pragma unroll
        for (int nt = 0; nt < 26; ++nt) {
            s[nt][0] = __uint_as_float(f2tf32(s[nt][0] * inv_lo));
            s[nt][1] = __uint_as_float(f2tf32(s[nt][1] * inv_lo));
            s[nt][2] = __uint_as_float(f2tf32(s[nt][2] * inv_hi));
            s[nt][3] = __uint_as_float(f2tf32(s[nt][3] * inv_hi));
        }

        float o[8][4];
        #pragma unroll
        for (int nt = 0; nt < 8; ++nt)
            #pragma unroll
            for (int i = 0; i < 4; ++i) o[nt][i] = 0.f;

        const int srcA = (gid << 2) | (qid >> 1);
        const int srcB = srcA + 2;
        const bool odd = (qid & 1);

        #pragma unroll
        for (int kt = 0; kt < 26; ++kt) {
            float lo, hi;
            lo = __shfl_sync(0xffffffffu, s[kt][0], srcA);
            hi = __shfl_sync(0xffffffffu, s[kt][1], srcA);
            const uint32_t a0 = __float_as_uint(odd ? hi : lo);
            lo = __shfl_sync(0xffffffffu, s[kt][2], srcA);
            hi = __shfl_sync(0xffffffffu, s[kt][3], srcA);
            const uint32_t a1 = __float_as_uint(odd ? hi : lo);
            lo = __shfl_sync(0xffffffffu, s[kt][0], srcB);
            hi = __shfl_sync(0xffffffffu, s[kt][1], srcB);
            const uint32_t a2 = __float_as_uint(odd ? hi : lo);
            lo = __shfl_sync(0xffffffffu, s[kt][2], srcB);
            hi = __shfl_sync(0xffffffffu, s[kt][3], srcB);
            const uint32_t a3 = __float_as_uint(odd ? hi : lo);

            const int kb = kt * 8;
            #pragma unroll
            for (int nt = 0; nt < 8; ++nt) {
                const uint32_t b0 =
                    __float_as_uint(Vs[(kb + qid    ) * SKV + nt * 8 + gid]);
                const uint32_t b1 =
                    __float_as_uint(Vs[(kb + qid + 4) * SKV + nt * 8 + gid]);
                mma_tf32(o[nt], a0, a1, a2, a3, b0, b1);
            }
        }

        #pragma unroll
        for (int nt = 0; nt < 8; ++nt) {
            const int cc = h * DH_ + nt * 8 + 2 * qid;
            if (r_lo < N_) {
                *(float2*)(outp + ((size_t)b * N_ + r_lo) * D_ + cc) =
                    make_float2(o[nt][0], o[nt][1]);
            }
            if (r_hi < N_) {
                *(float2*)(outp + ((size_t)b * N_ + r_hi) * D_ + cc) =
                    make_float2(o[nt][2], o[nt][3]);
            }
        }
    }
}

// ---------------------------------------------------------------------------
extern "C" void kernel_launch(void* const* d_in, const int* in_sizes, int n_in,
                              void* d_out, int out_size) {
    const float* x     = (const float*)d_in[0];
    const float* Wqkv  = (const float*)d_in[1];
    const float* scale = (const float*)d_in[2];
    const float* Wout  = (const float*)d_in[3];
    const float* bout  = (const float*)d_in[4];
    float* out = (float*)d_out;

    void* p_qkv  = nullptr;
    void* p_attn = nullptr;
    cudaGetSymbolAddress(&p_qkv,  g_qkv);
    cudaGetSymbolAddress(&p_attn, g_attn);
    float* qkv  = (float*)p_qkv;
    float* attn = (float*)p_attn;

    cudaFuncSetAttribute(gemm_tf32,
                         cudaFuncAttributeMaxDynamicSharedMemorySize,
                         GEMM_SMEM_BYTES);
    cudaFuncSetAttribute(attn_mma,
                         cudaFuncAttributeMaxDynamicSharedMemorySize,
                         ATTN_SMEM_BYTES);

    const int M = B_ * N_;  // 12608

    // 1) qkv = x @ W_qkv^T     [M, 2304]
    {
        dim3 grid(C3 / 128, (M + 127) / 128);
        gemm_tf32<<<grid, 256, GEMM_SMEM_BYTES>>>(x, Wqkv, nullptr, qkv,
                                                  M, C3, D_);
    }

    // 2) attention per (b, h)  -> attn [M, 768]
    {
        dim3 grid(H_, B_);
        attn_mma<<<grid, 256, ATTN_SMEM_BYTES>>>(qkv, scale, attn);
    }

    // 3) out = attn @ W_out^T + b_out   [M, 768]
    {
        dim3 grid(D_ / 128, (M + 127) / 128);
        gemm_tf32<<<grid, 256, GEMM_SMEM_BYTES>>>(attn, Wout, bout, out,
                                                  M, D_, D_);
    }
}

// round 6
// speedup vs baseline: 7.1797x; 2.1512x over previous
#include <cuda_runtime.h>
#include <cuda_fp16.h>
#include <cstdint>

#define B_  64
#define N_  197
#define D_  768
#define H_  12
#define DH_ 64
#define C3  2304          // 3*H*DH
#define MASK_VAL -987654321.0f

#define NP  208           // padded seq len (13 * 16)
#define SQK 72            // Qh/Kh smem row stride (halves)
#define SVT 216           // Vt smem row stride (halves)

// Scratch buffers (device globals: allocation-free contract)
__device__ __half g_qkvh [B_ * N_ * C3];   // fp16 qkv
__device__ __half g_attnh[B_ * N_ * D_];   // fp16 attention output
__device__ __half g_xh   [B_ * N_ * D_];   // fp16 x
__device__ __half g_wqkvh[C3 * D_];        // fp16 W_qkv
__device__ __half g_wouth[D_ * D_];        // fp16 W_out

// ===========================================================================
// Helpers
// ===========================================================================
__device__ __forceinline__ uint32_t smem_u32(const void* p) {
    return (uint32_t)__cvta_generic_to_shared(p);
}

__device__ __forceinline__ void mma_f16(float c[4],
                                        uint32_t a0, uint32_t a1,
                                        uint32_t a2, uint32_t a3,
                                        uint32_t b0, uint32_t b1) {
    asm volatile(
        "mma.sync.aligned.m16n8k16.row.col.f32.f16.f16.f32 "
        "{%0,%1,%2,%3}, {%4,%5,%6,%7}, {%8,%9}, {%0,%1,%2,%3};\n"
        : "+f"(c[0]), "+f"(c[1]), "+f"(c[2]), "+f"(c[3])
        : "r"(a0), "r"(a1), "r"(a2), "r"(a3), "r"(b0), "r"(b1));
}

__device__ __forceinline__ void ldsm_x4(uint32_t& r0, uint32_t& r1,
                                        uint32_t& r2, uint32_t& r3,
                                        uint32_t addr) {
    asm volatile(
        "ldmatrix.sync.aligned.m8n8.x4.shared.b16 {%0,%1,%2,%3}, [%4];"
        : "=r"(r0), "=r"(r1), "=r"(r2), "=r"(r3) : "r"(addr));
}

__device__ __forceinline__ void cp_async16(void* smem_dst, const void* gsrc,
                                           bool pred) {
    uint32_t saddr = smem_u32(smem_dst);
    int sz = pred ? 16 : 0;   // zfill when predicated off
    asm volatile("cp.async.ca.shared.global [%0], [%1], 16, %2;\n"
                 :: "r"(saddr), "l"(gsrc), "r"(sz));
}
__device__ __forceinline__ void cp_commit() {
    asm volatile("cp.async.commit_group;\n");
}
__device__ __forceinline__ void cp_wait0() {
    asm volatile("cp.async.wait_group 0;\n");
}

// ===========================================================================
// fp32 -> fp16 convert
// ===========================================================================
__global__ void __launch_bounds__(256)
f2h_kernel(const float* __restrict__ src, __half* __restrict__ dst) {
    const int i = blockIdx.x * 256 + threadIdx.x;
    float4 v = *(const float4*)(src + (size_t)i * 4);
    *reinterpret_cast<__half2*>(dst + (size_t)i * 4)     =
        __floats2half2_rn(v.x, v.y);
    *reinterpret_cast<__half2*>(dst + (size_t)i * 4 + 2) =
        __floats2half2_rn(v.z, v.w);
}

// ===========================================================================
// fp16 tensor-core GEMM (NT): C[m,n] = sum_k A[m,k]*W[n,k] (+ bias[n])
// 128x128 CTA tile, k64 chunks, 8 warps (2m x 4n), warp tile 64x32.
// Smem SW128-swizzled [128 rows][64 halves]; ldmatrix.x4 fragment loads;
// mma.m16n8k16 fp32 accum; cp.async double buffer.
// ===========================================================================
#define GT_K 64
#define TILE_B 16384                     // bytes per operand buffer
#define G16_SMEM (4 * TILE_B)            // 64 KB

__device__ __forceinline__ void g16_load(const __half* __restrict__ P,
                                         int ld, int base, int limit, int k0,
                                         char* sm, int tid) {
    #pragma unroll
    for (int i = 0; i < 4; ++i) {
        const int idx  = tid + i * 256;      // 0..1023
        const int row  = idx >> 3;           // 0..127
        const int c    = idx & 7;            // 16B chunk (8 halves)
        const int phys = c ^ (row & 7);
        const int gr   = base + row;
        const bool ok  = (limit < 0) || (gr < limit);
        const __half* src = P + (size_t)(ok ? gr : 0) * ld + k0 + c * 8;
        cp_async16(sm + row * 128 + phys * 16, src, ok);
    }
}

template <bool OUT_HALF>
__global__ void __launch_bounds__(256)
gemm_h16(const __half* __restrict__ A, const __half* __restrict__ W,
         const float* __restrict__ bias, void* __restrict__ Cv,
         int M, int N, int K) {
    extern __shared__ char smc[];
    const uint32_t sbase = smem_u32(smc);
    const int tid  = threadIdx.x;
    const int lane = tid & 31;
    const int wid  = tid >> 5;
    const int wm   = wid >> 2;           // 0..1
    const int wn   = wid & 3;            // 0..3
    const int gid  = lane >> 2;
    const int qid  = lane & 3;
    const int rowBase = blockIdx.y * 128;
    const int colBase = blockIdx.x * 128;

    float acc[4][4][4];
    #pragma unroll
    for (int i = 0; i < 4; ++i)
        #pragma unroll
        for (int j = 0; j < 4; ++j)
            #pragma unroll
            for (int r = 0; r < 4; ++r) acc[i][j][r] = 0.0f;

    const int T = K / GT_K;   // 12

    g16_load(A, K, rowBase, M,  0, smc,            tid);
    g16_load(W, K, colBase, -1, 0, smc + 2*TILE_B, tid);
    cp_commit();

    // ldmatrix lane address components
    const int a_row = (lane & 15);            // + wm*64 + mt*16
    const int a_ch  = (lane >> 4) & 1;        // + kt*2
    const int b_rowo = (lane & 7) + ((lane >> 4) & 1) * 8;  // + wn*32 + p*16
    const int b_ch  = (lane >> 3) & 1;        // + kt*2

    for (int t = 0; t < T; ++t) {
        cp_wait0();
        __syncthreads();
        if (t + 1 < T) {
            const int nb = (t + 1) & 1;
            g16_load(A, K, rowBase, M,  (t+1)*GT_K, smc + nb*TILE_B,       tid);
            g16_load(W, K, colBase, -1, (t+1)*GT_K, smc + 2*TILE_B + nb*TILE_B, tid);
            cp_commit();
        }

        const uint32_t sA = sbase + (t & 1) * TILE_B;
        const uint32_t sB = sbase + 2*TILE_B + (t & 1) * TILE_B;

        #pragma unroll
        for (int kt = 0; kt < 4; ++kt) {
            uint32_t af[4][4], bf[4][2];
            #pragma unroll
            for (int mt = 0; mt < 4; ++mt) {
                const int row = wm * 64 + mt * 16 + a_row;
                const int ch  = kt * 2 + a_ch;
                ldsm_x4(af[mt][0], af[mt][1], af[mt][2], af[mt][3],
                        sA + row * 128 + (ch ^ (row & 7)) * 16);
            }
            #pragma unroll
            for (int p = 0; p < 2; ++p) {
                const int row = wn * 32 + p * 16 + b_rowo;
                const int ch  = kt * 2 + b_ch;
                ldsm_x4(bf[2*p][0], bf[2*p][1], bf[2*p+1][0], bf[2*p+1][1],
                        sB + row * 128 + (ch ^ (row & 7)) * 16);
            }
            #pragma unroll
            for (int mt = 0; mt < 4; ++mt)
                #pragma unroll
                for (int nt = 0; nt < 4; ++nt)
                    mma_f16(acc[mt][nt], af[mt][0], af[mt][1], af[mt][2],
                            af[mt][3], bf[nt][0], bf[nt][1]);
        }
        __syncthreads();
    }

    // Epilogue
    #pragma unroll
    for (int mt = 0; mt < 4; ++mt) {
        #pragma unroll
        for (int nt = 0; nt < 4; ++nt) {
            const int r0 = rowBase + wm * 64 + mt * 16 + gid;
            const int r1 = r0 + 8;
            const int cc = colBase + wn * 32 + nt * 8 + qid * 2;
            if (OUT_HALF) {
                __half* C = (__half*)Cv;
                if (r0 < M)
                    *reinterpret_cast<__half2*>(C + (size_t)r0 * N + cc) =
                        __floats2half2_rn(acc[mt][nt][0], acc[mt][nt][1]);
                if (r1 < M)
                    *reinterpret_cast<__half2*>(C + (size_t)r1 * N + cc) =
                        __floats2half2_rn(acc[mt][nt][2], acc[mt][nt][3]);
            } else {
                float* C = (float*)Cv;
                float bx = 0.f, by = 0.f;
                if (bias) { bx = bias[cc]; by = bias[cc + 1]; }
                if (r0 < M)
                    *(float2*)(C + (size_t)r0 * N + cc) =
                        make_float2(acc[mt][nt][0] + bx, acc[mt][nt][1] + by);
                if (r1 < M)
                    *(float2*)(C + (size_t)r1 * N + cc) =
                        make_float2(acc[mt][nt][2] + bx, acc[mt][nt][3] + by);
            }
        }
    }
}

// ===========================================================================
// fp16 tensor-core attention: one CTA per (b, h), 8 warps, 2 CTAs/SM.
// Qh/Kh [NP][72] fp16; Vt [64][216] fp16 (transposed). S in accumulators;
// in-register softmax; P packed half2 in place (C layout == A-frag layout
// for m16n8k16 -> no transpose); PV mma -> fp16 output.
// ===========================================================================
#define ATTN_SMEM_BYTES ((2 * NP * SQK + DH_ * SVT) * 2)   // 87552

__global__ void __launch_bounds__(256, 2)
attn_h(const __half* __restrict__ qkvh, const float* __restrict__ scale,
       __half* __restrict__ outp) {
    extern __shared__ __half smh[];
    __half* Qh = smh;
    __half* Kh = smh + NP * SQK;
    __half* Vt = smh + 2 * NP * SQK;

    const int b = blockIdx.y;
    const int h = blockIdx.x;
    const int tid  = threadIdx.x;
    const int w    = tid >> 5;
    const int lane = tid & 31;
    const int gid  = lane >> 2;
    const int qid  = lane & 3;
    const float sc = scale[h];

    const __half* base = qkvh + (size_t)b * N_ * C3 + h * DH_;

    for (int idx = tid; idx < NP * DH_; idx += 256) {
        const int row = idx >> 6;
        const int d   = idx & 63;
        __half q = __float2half(0.f), k = q, v = q;
        if (row < N_) {
            const __half* p = base + (size_t)row * C3 + d;
            q = p[0];
            k = p[D_];
            v = p[2 * D_];
        }
        Qh[row * SQK + d] = __float2half(__half2float(q) * sc);
        Kh[row * SQK + d] = k;
        Vt[d * SVT + row] = v;
    }
    __syncthreads();

    for (int c = w; c < 13; c += 8) {
        const int m0 = c * 16;
        const int r_lo = m0 + gid;
        const int r_hi = r_lo + 8;

        // ---- S = Q K^T ----
        float s[26][4];
        #pragma unroll
        for (int nt = 0; nt < 26; ++nt)
            #pragma unroll
            for (int i = 0; i < 4; ++i) s[nt][i] = 0.f;

        #pragma unroll
        for (int kt = 0; kt < 4; ++kt) {
            const int kb = kt * 16;
            const uint32_t a0 = *(const uint32_t*)&Qh[r_lo * SQK + kb + 2*qid    ];
            const uint32_t a1 = *(const uint32_t*)&Qh[r_hi * SQK + kb + 2*qid    ];
            const uint32_t a2 = *(const uint32_t*)&Qh[r_lo * SQK + kb + 2*qid + 8];
            const uint32_t a3 = *(const uint32_t*)&Qh[r_hi * SQK + kb + 2*qid + 8];
            #pragma unroll
            for (int nt = 0; nt < 26; ++nt) {
                const __half* kr = &Kh[(nt * 8 + gid) * SQK + kb + 2*qid];
                const uint32_t b0 = *(const uint32_t*)(kr);
                const uint32_t b1 = *(const uint32_t*)(kr + 8);
                mma_f16(s[nt], a0, a1, a2, a3, b0, b1);
            }
        }

        // ---- mask + softmax ----
        float mx_lo = -3.0e38f, mx_hi = -3.0e38f;
        #pragma unroll
        for (int nt = 0; nt < 26; ++nt) {
            const int j0 = nt * 8 + 2 * qid;
            const int j1 = j0 + 1;
            float v0 = s[nt][0], v1 = s[nt][1], v2 = s[nt][2], v3 = s[nt][3];
            v0 = (j0 >= N_) ? -3.0e38f : ((j0 == r_lo) ? MASK_VAL : v0);
            v1 = (j1 >= N_) ? -3.0e38f : ((j1 == r_lo) ? MASK_VAL : v1);
            v2 = (j0 >= N_) ? -3.0e38f : ((j0 == r_hi) ? MASK_VAL : v2);
            v3 = (j1 >= N_) ? -3.0e38f : ((j1 == r_hi) ? MASK_VAL : v3);
            s[nt][0] = v0; s[nt][1] = v1; s[nt][2] = v2; s[nt][3] = v3;
            mx_lo = fmaxf(mx_lo, fmaxf(v0, v1));
            mx_hi = fmaxf(mx_hi, fmaxf(v2, v3));
        }
        mx_lo = fmaxf(mx_lo, __shfl_xor_sync(0xffffffffu, mx_lo, 1));
        mx_lo = fmaxf(mx_lo, __shfl_xor_sync(0xffffffffu, mx_lo, 2));
        mx_hi = fmaxf(mx_hi, __shfl_xor_sync(0xffffffffu, mx_hi, 1));
        mx_hi = fmaxf(mx_hi, __shfl_xor_sync(0xffffffffu, mx_hi, 2));

        float sum_lo = 0.f, sum_hi = 0.f;
        #pragma unroll
        for (int nt = 0; nt < 26; ++nt) {
            float e0 = __expf(s[nt][0] - mx_lo);
            float e1 = __expf(s[nt][1] - mx_lo);
            float e2 = __expf(s[nt][2] - mx_hi);
            float e3 = __expf(s[nt][3] - mx_hi);
            s[nt][0] = e0; s[nt][1] = e1; s[nt][2] = e2; s[nt][3] = e3;
            sum_lo += e0 + e1;
            sum_hi += e2 + e3;
        }
        sum_lo += __shfl_xor_sync(0xffffffffu, sum_lo, 1);
        sum_lo += __shfl_xor_sync(0xffffffffu, sum_lo, 2);
        sum_hi += __shfl_xor_sync(0xffffffffu, sum_hi, 1);
        sum_hi += __shfl_xor_sync(0xffffffffu, sum_hi, 2);
        const float inv_lo = 1.0f / sum_lo;
        const float inv_hi = 1.0f / sum_hi;

        // ---- pack P to half2 in place: s[nt][0] <- (p0,p1), s[nt][1] <- (p2,p3)
        #pragma unroll
        for (int nt = 0; nt < 26; ++nt) {
            __half2 plo = __floats2half2_rn(s[nt][0] * inv_lo, s[nt][1] * inv_lo);
            __half2 phi = __floats2half2_rn(s[nt][2] * inv_hi, s[nt][3] * inv_hi);
            s[nt][0] = __uint_as_float(*(uint32_t*)&plo);
            s[nt][1] = __uint_as_float(*(uint32_t*)&phi);
        }

        // ---- O = P V ----
        float o[8][4];
        #pragma unroll
        for (int nt = 0; nt < 8; ++nt)
            #pragma unroll
            for (int i = 0; i < 4; ++i) o[nt][i] = 0.f;

        #pragma unroll
        for (int kt = 0; kt < 13; ++kt) {
            const uint32_t a0 = __float_as_uint(s[2*kt    ][0]);
            const uint32_t a1 = __float_as_uint(s[2*kt    ][1]);
            const uint32_t a2 = __float_as_uint(s[2*kt + 1][0]);
            const uint32_t a3 = __float_as_uint(s[2*kt + 1][1]);
            const int kb = kt * 16;
            #pragma unroll
            for (int nt = 0; nt < 8; ++nt) {
                const __half* vr = &Vt[(nt * 8 + gid) * SVT + kb + 2*qid];
                const uint32_t b0 = *(const uint32_t*)(vr);
                const uint32_t b1 = *(const uint32_t*)(vr + 8);
                mma_f16(o[nt], a0, a1, a2, a3, b0, b1);
            }
        }

        // ---- store (fp16) ----
        #pragma unroll
        for (int nt = 0; nt < 8; ++nt) {
            const int cc = h * DH_ + nt * 8 + 2 * qid;
            if (r_lo < N_)
                *reinterpret_cast<__half2*>(
                    outp + ((size_t)b * N_ + r_lo) * D_ + cc) =
                    __floats2half2_rn(o[nt][0], o[nt][1]);
            if (r_hi < N_)
                *reinterpret_cast<__half2*>(
                    outp + ((size_t)b * N_ + r_hi) * D_ + cc) =
                    __floats2half2_rn(o[nt][2], o[nt][3]);
        }
    }
}

// ===========================================================================
extern "C" void kernel_launch(void* const* d_in, const int* in_sizes, int n_in,
                              void* d_out, int out_size) {
    const float* x     = (const float*)d_in[0];
    const float* Wqkv  = (const float*)d_in[1];
    const float* scale = (const float*)d_in[2];
    const float* Wout  = (const float*)d_in[3];
    const float* bout  = (const float*)d_in[4];
    float* out = (float*)d_out;

    void *p_qkvh, *p_attnh, *p_xh, *p_wqkvh, *p_wouth;
    cudaGetSymbolAddress(&p_qkvh,  g_qkvh);
    cudaGetSymbolAddress(&p_attnh, g_attnh);
    cudaGetSymbolAddress(&p_xh,    g_xh);
    cudaGetSymbolAddress(&p_wqkvh, g_wqkvh);
    cudaGetSymbolAddress(&p_wouth, g_wouth);
    __half* qkvh  = (__half*)p_qkvh;
    __half* attnh = (__half*)p_attnh;
    __half* xh    = (__half*)p_xh;
    __half* wqkvh = (__half*)p_wqkvh;
    __half* wouth = (__half*)p_wouth;

    cudaFuncSetAttribute(gemm_h16<true>,
                         cudaFuncAttributeMaxDynamicSharedMemorySize, G16_SMEM);
    cudaFuncSetAttribute(gemm_h16<false>,
                         cudaFuncAttributeMaxDynamicSharedMemorySize, G16_SMEM);
    cudaFuncSetAttribute(attn_h,
                         cudaFuncAttributeMaxDynamicSharedMemorySize,
                         ATTN_SMEM_BYTES);

    const int M = B_ * N_;  // 12608

    // 0) fp32 -> fp16 converts
    f2h_kernel<<<(B_ * N_ * D_) / 1024, 256>>>(x, xh);
    f2h_kernel<<<(C3 * D_) / 1024, 256>>>(Wqkv, wqkvh);
    f2h_kernel<<<(D_ * D_) / 1024, 256>>>(Wout, wouth);

    // 1) qkv = x @ W_qkv^T   [M, 2304] fp16
    {
        dim3 grid(C3 / 128, (M + 127) / 128);
        gemm_h16<true><<<grid, 256, G16_SMEM>>>(xh, wqkvh, nullptr, qkvh,
                                                M, C3, D_);
    }

    // 2) attention per (b, h) -> attnh [M, 768] fp16
    {
        dim3 grid(H_, B_);
        attn_h<<<grid, 256, ATTN_SMEM_BYTES>>>(qkvh, scale, attnh);
    }

    // 3) out = attn @ W_out^T + b_out   [M, 768] fp32
    {
        dim3 grid(D_ / 128, (M + 127) / 128);
        gemm_h16<false><<<grid, 256, G16_SMEM>>>(attnh, wouth, bout, out,
                                                 M, D_, D_);
    }
}

// round 7
// speedup vs baseline: 7.1993x; 1.0027x over previous
#include <cuda_runtime.h>
#include <cuda_fp16.h>
#include <cstdint>

#define B_  64
#define N_  197
#define D_  768
#define H_  12
#define DH_ 64
#define C3  2304          // 3*H*DH
#define MASK_VAL -987654321.0f

#define NP  208           // padded seq len (13 * 16)
#define SQK 72            // Qh/Kh smem row stride (halves)
#define SVT 216           // Vt smem row stride (halves)

// Scratch buffers (device globals: allocation-free contract)
__device__ __half g_qkvh [B_ * N_ * C3];   // fp16 qkv
__device__ __half g_attnh[B_ * N_ * D_];   // fp16 attention output
__device__ __half g_xh   [B_ * N_ * D_];   // fp16 x
__device__ __half g_wqkvh[C3 * D_];        // fp16 W_qkv
__device__ __half g_wouth[D_ * D_];        // fp16 W_out

// ===========================================================================
// Helpers
// ===========================================================================
__device__ __forceinline__ uint32_t smem_u32(const void* p) {
    return (uint32_t)__cvta_generic_to_shared(p);
}

__device__ __forceinline__ void mma_f16(float c[4],
                                        uint32_t a0, uint32_t a1,
                                        uint32_t a2, uint32_t a3,
                                        uint32_t b0, uint32_t b1) {
    asm volatile(
        "mma.sync.aligned.m16n8k16.row.col.f32.f16.f16.f32 "
        "{%0,%1,%2,%3}, {%4,%5,%6,%7}, {%8,%9}, {%0,%1,%2,%3};\n"
        : "+f"(c[0]), "+f"(c[1]), "+f"(c[2]), "+f"(c[3])
        : "r"(a0), "r"(a1), "r"(a2), "r"(a3), "r"(b0), "r"(b1));
}

__device__ __forceinline__ void ldsm_x4(uint32_t& r0, uint32_t& r1,
                                        uint32_t& r2, uint32_t& r3,
                                        uint32_t addr) {
    asm volatile(
        "ldmatrix.sync.aligned.m8n8.x4.shared.b16 {%0,%1,%2,%3}, [%4];"
        : "=r"(r0), "=r"(r1), "=r"(r2), "=r"(r3) : "r"(addr));
}

__device__ __forceinline__ void cp_async16(void* smem_dst, const void* gsrc,
                                           bool pred) {
    uint32_t saddr = smem_u32(smem_dst);
    int sz = pred ? 16 : 0;   // zfill when predicated off
    asm volatile("cp.async.ca.shared.global [%0], [%1], 16, %2;\n"
                 :: "r"(saddr), "l"(gsrc), "r"(sz));
}
__device__ __forceinline__ void cp_commit() {
    asm volatile("cp.async.commit_group;\n");
}
__device__ __forceinline__ void cp_wait0() {
    asm volatile("cp.async.wait_group 0;\n");
}

// ===========================================================================
// fp32 -> fp16 convert
// ===========================================================================
__global__ void __launch_bounds__(256)
f2h_kernel(const float* __restrict__ src, __half* __restrict__ dst) {
    const int i = blockIdx.x * 256 + threadIdx.x;
    float4 v = *(const float4*)(src + (size_t)i * 4);
    *reinterpret_cast<__half2*>(dst + (size_t)i * 4)     =
        __floats2half2_rn(v.x, v.y);
    *reinterpret_cast<__half2*>(dst + (size_t)i * 4 + 2) =
        __floats2half2_rn(v.z, v.w);
}

// ===========================================================================
// fp16 tensor-core GEMM (NT): C[m,n] = sum_k A[m,k]*W[n,k] (+ bias[n])
// 128x128 CTA tile, k64 chunks, 8 warps (2m x 4n), warp tile 64x32.
// Smem SW128-swizzled [128 rows][64 halves]; ldmatrix.x4 fragment loads;
// mma.m16n8k16 fp32 accum; cp.async double buffer.
// ===========================================================================
#define GT_K 64
#define TILE_B 16384                     // bytes per operand buffer
#define G16_SMEM (4 * TILE_B)            // 64 KB

__device__ __forceinline__ void g16_load(const __half* __restrict__ P,
                                         int ld, int base, int limit, int k0,
                                         char* sm, int tid) {
    #pragma unroll
    for (int i = 0; i < 4; ++i) {
        const int idx  = tid + i * 256;      // 0..1023
        const int row  = idx >> 3;           // 0..127
        const int c    = idx & 7;            // 16B chunk (8 halves)
        const int phys = c ^ (row & 7);
        const int gr   = base + row;
        const bool ok  = (limit < 0) || (gr < limit);
        const __half* src = P + (size_t)(ok ? gr : 0) * ld + k0 + c * 8;
        cp_async16(sm + row * 128 + phys * 16, src, ok);
    }
}

template <bool OUT_HALF>
__global__ void __launch_bounds__(256)
gemm_h16(const __half* __restrict__ A, const __half* __restrict__ W,
         const float* __restrict__ bias, void* __restrict__ Cv,
         int M, int N, int K) {
    extern __shared__ char smc[];
    const uint32_t sbase = smem_u32(smc);
    const int tid  = threadIdx.x;
    const int lane = tid & 31;
    const int wid  = tid >> 5;
    const int wm   = wid >> 2;           // 0..1
    const int wn   = wid & 3;            // 0..3
    const int gid  = lane >> 2;
    const int qid  = lane & 3;
    const int rowBase = blockIdx.y * 128;
    const int colBase = blockIdx.x * 128;

    float acc[4][4][4];
    #pragma unroll
    for (int i = 0; i < 4; ++i)
        #pragma unroll
        for (int j = 0; j < 4; ++j)
            #pragma unroll
            for (int r = 0; r < 4; ++r) acc[i][j][r] = 0.0f;

    const int T = K / GT_K;   // 12

    g16_load(A, K, rowBase, M,  0, smc,            tid);
    g16_load(W, K, colBase, -1, 0, smc + 2*TILE_B, tid);
    cp_commit();

    // ldmatrix lane address components
    const int a_row = (lane & 15);            // + wm*64 + mt*16
    const int a_ch  = (lane >> 4) & 1;        // + kt*2
    const int b_rowo = (lane & 7) + ((lane >> 4) & 1) * 8;  // + wn*32 + p*16
    const int b_ch  = (lane >> 3) & 1;        // + kt*2

    for (int t = 0; t < T; ++t) {
        cp_wait0();
        __syncthreads();
        if (t + 1 < T) {
            const int nb = (t + 1) & 1;
            g16_load(A, K, rowBase, M,  (t+1)*GT_K, smc + nb*TILE_B,       tid);
            g16_load(W, K, colBase, -1, (t+1)*GT_K, smc + 2*TILE_B + nb*TILE_B, tid);
            cp_commit();
        }

        const uint32_t sA = sbase + (t & 1) * TILE_B;
        const uint32_t sB = sbase + 2*TILE_B + (t & 1) * TILE_B;

        #pragma unroll
        for (int kt = 0; kt < 4; ++kt) {
            uint32_t af[4][4], bf[4][2];
            #pragma unroll
            for (int mt = 0; mt < 4; ++mt) {
                const int row = wm * 64 + mt * 16 + a_row;
                const int ch  = kt * 2 + a_ch;
                ldsm_x4(af[mt][0], af[mt][1], af[mt][2], af[mt][3],
                        sA + row * 128 + (ch ^ (row & 7)) * 16);
            }
            #pragma unroll
            for (int p = 0; p < 2; ++p) {
                const int row = wn * 32 + p * 16 + b_rowo;
                const int ch  = kt * 2 + b_ch;
                ldsm_x4(bf[2*p][0], bf[2*p][1], bf[2*p+1][0], bf[2*p+1][1],
                        sB + row * 128 + (ch ^ (row & 7)) * 16);
            }
            #pragma unroll
            for (int mt = 0; mt < 4; ++mt)
                #pragma unroll
                for (int nt = 0; nt < 4; ++nt)
                    mma_f16(acc[mt][nt], af[mt][0], af[mt][1], af[mt][2],
                            af[mt][3], bf[nt][0], bf[nt][1]);
        }
        __syncthreads();
    }

    // Epilogue
    #pragma unroll
    for (int mt = 0; mt < 4; ++mt) {
        #pragma unroll
        for (int nt = 0; nt < 4; ++nt) {
            const int r0 = rowBase + wm * 64 + mt * 16 + gid;
            const int r1 = r0 + 8;
            const int cc = colBase + wn * 32 + nt * 8 + qid * 2;
            if (OUT_HALF) {
                __half* C = (__half*)Cv;
                if (r0 < M)
                    *reinterpret_cast<__half2*>(C + (size_t)r0 * N + cc) =
                        __floats2half2_rn(acc[mt][nt][0], acc[mt][nt][1]);
                if (r1 < M)
                    *reinterpret_cast<__half2*>(C + (size_t)r1 * N + cc) =
                        __floats2half2_rn(acc[mt][nt][2], acc[mt][nt][3]);
            } else {
                float* C = (float*)Cv;
                float bx = 0.f, by = 0.f;
                if (bias) { bx = bias[cc]; by = bias[cc + 1]; }
                if (r0 < M)
                    *(float2*)(C + (size_t)r0 * N + cc) =
                        make_float2(acc[mt][nt][0] + bx, acc[mt][nt][1] + by);
                if (r1 < M)
                    *(float2*)(C + (size_t)r1 * N + cc) =
                        make_float2(acc[mt][nt][2] + bx, acc[mt][nt][3] + by);
            }
        }
    }
}

// ===========================================================================
// fp16 tensor-core attention: one CTA per (b, h), 8 warps, 2 CTAs/SM.
// Qh/Kh [NP][72] fp16; Vt [64][216] fp16 (transposed). S in accumulators;
// in-register softmax; P packed half2 in place (C layout == A-frag layout
// for m16n8k16 -> no transpose); PV mma -> fp16 output.
// ===========================================================================
#define ATTN_SMEM_BYTES ((2 * NP * SQK + DH_ * SVT) * 2)   // 87552

__global__ void __launch_bounds__(256, 2)
attn_h(const __half* __restrict__ qkvh, const float* __restrict__ scale,
       __half* __restrict__ outp) {
    extern __shared__ __half smh[];
    __half* Qh = smh;
    __half* Kh = smh + NP * SQK;
    __half* Vt = smh + 2 * NP * SQK;

    const int b = blockIdx.y;
    const int h = blockIdx.x;
    const int tid  = threadIdx.x;
    const int w    = tid >> 5;
    const int lane = tid & 31;
    const int gid  = lane >> 2;
    const int qid  = lane & 3;
    const float sc = scale[h];

    const __half* base = qkvh + (size_t)b * N_ * C3 + h * DH_;

    for (int idx = tid; idx < NP * DH_; idx += 256) {
        const int row = idx >> 6;
        const int d   = idx & 63;
        __half q = __float2half(0.f), k = q, v = q;
        if (row < N_) {
            const __half* p = base + (size_t)row * C3 + d;
            q = p[0];
            k = p[D_];
            v = p[2 * D_];
        }
        Qh[row * SQK + d] = __float2half(__half2float(q) * sc);
        Kh[row * SQK + d] = k;
        Vt[d * SVT + row] = v;
    }
    __syncthreads();

    for (int c = w; c < 13; c += 8) {
        const int m0 = c * 16;
        const int r_lo = m0 + gid;
        const int r_hi = r_lo + 8;

        // ---- S = Q K^T ----
        float s[26][4];
        #pragma unroll
        for (int nt = 0; nt < 26; ++nt)
            #pragma unroll
            for (int i = 0; i < 4; ++i) s[nt][i] = 0.f;

        #pragma unroll
        for (int kt = 0; kt < 4; ++kt) {
            const int kb = kt * 16;
            const uint32_t a0 = *(const uint32_t*)&Qh[r_lo * SQK + kb + 2*qid    ];
            const uint32_t a1 = *(const uint32_t*)&Qh[r_hi * SQK + kb + 2*qid    ];
            const uint32_t a2 = *(const uint32_t*)&Qh[r_lo * SQK + kb + 2*qid + 8];
            const uint32_t a3 = *(const uint32_t*)&Qh[r_hi * SQK + kb + 2*qid + 8];
            #pragma unroll
            for (int nt = 0; nt < 26; ++nt) {
                const __half* kr = &Kh[(nt * 8 + gid) * SQK + kb + 2*qid];
                const uint32_t b0 = *(const uint32_t*)(kr);
                const uint32_t b1 = *(const uint32_t*)(kr + 8);
                mma_f16(s[nt], a0, a1, a2, a3, b0, b1);
            }
        }

        // ---- mask + softmax ----
        float mx_lo = -3.0e38f, mx_hi = -3.0e38f;
        #pragma unroll
        for (int nt = 0; nt < 26; ++nt) {
            const int j0 = nt * 8 + 2 * qid;
            const int j1 = j0 + 1;
            float v0 = s[nt][0], v1 = s[nt][1], v2 = s[nt][2], v3 = s[nt][3];
            v0 = (j0 >= N_) ? -3.0e38f : ((j0 == r_lo) ? MASK_VAL : v0);
            v1 = (j1 >= N_) ? -3.0e38f : ((j1 == r_lo) ? MASK_VAL : v1);
            v2 = (j0 >= N_) ? -3.0e38f : ((j0 == r_hi) ? MASK_VAL : v2);
            v3 = (j1 >= N_) ? -3.0e38f : ((j1 == r_hi) ? MASK_VAL : v3);
            s[nt][0] = v0; s[nt][1] = v1; s[nt][2] = v2; s[nt][3] = v3;
            mx_lo = fmaxf(mx_lo, fmaxf(v0, v1));
            mx_hi = fmaxf(mx_hi, fmaxf(v2, v3));
        }
        mx_lo = fmaxf(mx_lo, __shfl_xor_sync(0xffffffffu, mx_lo, 1));
        mx_lo = fmaxf(mx_lo, __shfl_xor_sync(0xffffffffu, mx_lo, 2));
        mx_hi = fmaxf(mx_hi, __shfl_xor_sync(0xffffffffu, mx_hi, 1));
        mx_hi = fmaxf(mx_hi, __shfl_xor_sync(0xffffffffu, mx_hi, 2));

        float sum_lo = 0.f, sum_hi = 0.f;
        #pragma unroll
        for (int nt = 0; nt < 26; ++nt) {
            float e0 = __expf(s[nt][0] - mx_lo);
            float e1 = __expf(s[nt][1] - mx_lo);
            float e2 = __expf(s[nt][2] - mx_hi);
            float e3 = __expf(s[nt][3] - mx_hi);
            s[nt][0] = e0; s[nt][1] = e1; s[nt][2] = e2; s[nt][3] = e3;
            sum_lo += e0 + e1;
            sum_hi += e2 + e3;
        }
        sum_lo += __shfl_xor_sync(0xffffffffu, sum_lo, 1);
        sum_lo += __shfl_xor_sync(0xffffffffu, sum_lo, 2);
        sum_hi += __shfl_xor_sync(0xffffffffu, sum_hi, 1);
        sum_hi += __shfl_xor_sync(0xffffffffu, sum_hi, 2);
        const float inv_lo = 1.0f / sum_lo;
        const float inv_hi = 1.0f / sum_hi;

        // ---- pack P to half2 in place: s[nt][0] <- (p0,p1), s[nt][1] <- (p2,p3)
        #pragma unroll
        for (int nt = 0; nt < 26; ++nt) {
            __half2 plo = __floats2half2_rn(s[nt][0] * inv_lo, s[nt][1] * inv_lo);
            __half2 phi = __floats2half2_rn(s[nt][2] * inv_hi, s[nt][3] * inv_hi);
            s[nt][0] = __uint_as_float(*(uint32_t*)&plo);
            s[nt][1] = __uint_as_float(*(uint32_t*)&phi);
        }

        // ---- O = P V ----
        float o[8][4];
        #pragma unroll
        for (int nt = 0; nt < 8; ++nt)
            #pragma unroll
            for (int i = 0; i < 4; ++i) o[nt][i] = 0.f;

        #pragma unroll
        for (int kt = 0; kt < 13; ++kt) {
            const uint32_t a0 = __float_as_uint(s[2*kt    ][0]);
            const uint32_t a1 = __float_as_uint(s[2*kt    ][1]);
            const uint32_t a2 = __float_as_uint(s[2*kt + 1][0]);
            const uint32_t a3 = __float_as_uint(s[2*kt + 1][1]);
            const int kb = kt * 16;
            #pragma unroll
            for (int nt = 0; nt < 8; ++nt) {
                const __half* vr = &Vt[(nt * 8 + gid) * SVT + kb + 2*qid];
                const uint32_t b0 = *(const uint32_t*)(vr);
                const uint32_t b1 = *(const uint32_t*)(vr + 8);
                mma_f16(o[nt], a0, a1, a2, a3, b0, b1);
            }
        }

        // ---- store (fp16) ----
        #pragma unroll
        for (int nt = 0; nt < 8; ++nt) {
            const int cc = h * DH_ + nt * 8 + 2 * qid;
            if (r_lo < N_)
                *reinterpret_cast<__half2*>(
                    outp + ((size_t)b * N_ + r_lo) * D_ + cc) =
                    __floats2half2_rn(o[nt][0], o[nt][1]);
            if (r_hi < N_)
                *reinterpret_cast<__half2*>(
                    outp + ((size_t)b * N_ + r_hi) * D_ + cc) =
                    __floats2half2_rn(o[nt][2], o[nt][3]);
        }
    }
}

// ===========================================================================
extern "C" void kernel_launch(void* const* d_in, const int* in_sizes, int n_in,
                              void* d_out, int out_size) {
    const float* x     = (const float*)d_in[0];
    const float* Wqkv  = (const float*)d_in[1];
    const float* scale = (const float*)d_in[2];
    const float* Wout  = (const float*)d_in[3];
    const float* bout  = (const float*)d_in[4];
    float* out = (float*)d_out;

    void *p_qkvh, *p_attnh, *p_xh, *p_wqkvh, *p_wouth;
    cudaGetSymbolAddress(&p_qkvh,  g_qkvh);
    cudaGetSymbolAddress(&p_attnh, g_attnh);
    cudaGetSymbolAddress(&p_xh,    g_xh);
    cudaGetSymbolAddress(&p_wqkvh, g_wqkvh);
    cudaGetSymbolAddress(&p_wouth, g_wouth);
    __half* qkvh  = (__half*)p_qkvh;
    __half* attnh = (__half*)p_attnh;
    __half* xh    = (__half*)p_xh;
    __half* wqkvh = (__half*)p_wqkvh;
    __half* wouth = (__half*)p_wouth;

    cudaFuncSetAttribute(gemm_h16<true>,
                         cudaFuncAttributeMaxDynamicSharedMemorySize, G16_SMEM);
    cudaFuncSetAttribute(gemm_h16<false>,
                         cudaFuncAttributeMaxDynamicSharedMemorySize, G16_SMEM);
    cudaFuncSetAttribute(attn_h,
                         cudaFuncAttributeMaxDynamicSharedMemorySize,
                         ATTN_SMEM_BYTES);

    const int M = B_ * N_;  // 12608

    // 0) fp32 -> fp16 converts
    f2h_kernel<<<(B_ * N_ * D_) / 1024, 256>>>(x, xh);
    f2h_kernel<<<(C3 * D_) / 1024, 256>>>(Wqkv, wqkvh);
    f2h_kernel<<<(D_ * D_) / 1024, 256>>>(Wout, wouth);

    // 1) qkv = x @ W_qkv^T   [M, 2304] fp16
    {
        dim3 grid(C3 / 128, (M + 127) / 128);
        gemm_h16<true><<<grid, 256, G16_SMEM>>>(xh, wqkvh, nullptr, qkvh,
                                                M, C3, D_);
    }

    // 2) attention per (b, h) -> attnh [M, 768] fp16
    {
        dim3 grid(H_, B_);
        attn_h<<<grid, 256, ATTN_SMEM_BYTES>>>(qkvh, scale, attnh);
    }

    // 3) out = attn @ W_out^T + b_out   [M, 768] fp32
    {
        dim3 grid(D_ / 128, (M + 127) / 128);
        gemm_h16<false><<<grid, 256, G16_SMEM>>>(attnh, wouth, bout, out,
                                                 M, D_, D_);
    }
}